// round 15
// baseline (speedup 1.0000x reference)
#include <cuda_runtime.h>
#include <cuda_fp16.h>
#include <cstdint>

// ---------------------------------------------------------------------------
// Problem constants
// ---------------------------------------------------------------------------
#define BATCH 4
#define SEQ   4096
#define DMODEL 512
#define PROJD  512
#define MFLAT (BATCH * SEQ)
#define SCALE_QK 0.125f
#define EXP_SHIFT 12.0f

// ---------------------------------------------------------------------------
// Scratch (device globals)
// ---------------------------------------------------------------------------
__device__ __align__(16) __half g_qh [MFLAT * DMODEL];
__device__ __align__(16) __half g_ql [MFLAT * DMODEL];
__device__ __align__(16) __half g_kh [MFLAT * DMODEL];
__device__ __align__(16) __half g_kl [MFLAT * DMODEL];
__device__ __align__(16) __half g_vh [MFLAT * DMODEL];
__device__ __align__(16) __half g_vl [MFLAT * DMODEL];
__device__ __align__(16) __half g_wqh[PROJD * DMODEL];
__device__ __align__(16) __half g_wql[PROJD * DMODEL];
__device__ __align__(16) __half g_wkh[PROJD * DMODEL];
__device__ __align__(16) __half g_wkl[PROJD * DMODEL];
__device__ __align__(16) __half g_wvh[PROJD * DMODEL];
__device__ __align__(16) __half g_wvl[PROJD * DMODEL];
__device__ __align__(16) __half g_wmh[DMODEL * PROJD];
__device__ __align__(16) __half g_wml[DMODEL * PROJD];
__device__ __align__(16) __half g_qph[MFLAT * PROJD];
__device__ __align__(16) __half g_qpl[MFLAT * PROJD];
__device__ __align__(16) __half g_kph[MFLAT * PROJD];
__device__ __align__(16) __half g_kpl[MFLAT * PROJD];
__device__ __align__(16) __half g_vTh[MFLAT * PROJD];              // per-batch [512][4096]
__device__ __align__(16) __half g_Ph[(size_t)BATCH * SEQ * SEQ];   // exp(s-12), fp16
__device__ __align__(16) __half g_dh [MFLAT * PROJD];
__device__ float g_part[(size_t)MFLAT * 64];                       // per-row partial sums
__device__ float g_rowsum[MFLAT];

// ---------------------------------------------------------------------------
// Helpers
// ---------------------------------------------------------------------------
__device__ __forceinline__ uint32_t smem_u32(const void* p) {
    uint32_t a;
    asm("{ .reg .u64 t; cvta.to.shared.u64 t, %1; cvt.u32.u64 %0, t; }"
        : "=r"(a) : "l"(p));
    return a;
}

__device__ __forceinline__ void split2(float x, float y, uint32_t& hi, uint32_t& lo) {
    __half2 h = __floats2half2_rn(x, y);
    float2  f = __half22float2(h);
    __half2 l = __floats2half2_rn(x - f.x, y - f.y);
    hi = *(uint32_t*)&h;
    lo = *(uint32_t*)&l;
}

__device__ __forceinline__ void mma_f16(float* d, const uint32_t* a, const uint32_t* b) {
    asm volatile(
        "mma.sync.aligned.m16n8k16.row.col.f32.f16.f16.f32 "
        "{%0,%1,%2,%3}, {%4,%5,%6,%7}, {%8,%9}, {%0,%1,%2,%3};\n"
        : "+f"(d[0]), "+f"(d[1]), "+f"(d[2]), "+f"(d[3])
        : "r"(a[0]), "r"(a[1]), "r"(a[2]), "r"(a[3]),
          "r"(b[0]), "r"(b[1]));
}

#define LDM4(r, addr) \
    asm volatile("ldmatrix.sync.aligned.m8n8.x4.shared.b16 {%0,%1,%2,%3}, [%4];" \
        : "=r"((r)[0]), "=r"((r)[1]), "=r"((r)[2]), "=r"((r)[3]) : "r"(addr))

#define CP_COMMIT() asm volatile("cp.async.commit_group;" ::: "memory")
#define CP_WAIT(n)  asm volatile("cp.async.wait_group %0;" :: "n"(n) : "memory")

// ---------------------------------------------------------------------------
// Tile geometry, now templated:
//   TERMS>=2: ROWB=144 (hi 64B | lo 64B | pad 16B), 3 stages  (110.6 KB)
//   TERMS==1: ROWB=80  (hi 64B | pad 16B),          4 stages  ( 81.9 KB)
// CTA 128x128, BK=32, 8 warps (4M x 2N), 2 CTA/SM in all cases.
// ---------------------------------------------------------------------------
#define SMEM_T3 (3 * 2 * 128 * 144)   // 110592
#define SMEM_T1 (4 * 2 * 128 * 80)    //  81920

template <int TERMS, int RB>
__device__ __forceinline__ void cp_issue(uint32_t sbase,
    const __half* __restrict__ Ah, const __half* __restrict__ Al,
    const __half* __restrict__ Bh, const __half* __restrict__ Bl,
    int k0, int K, int tid)
{
    constexpr int TILE = 128 * RB;
    if (TERMS == 1) {
        // 1024 x 16B chunks: A 512 (128 rows x 4 segs), B 512
        #pragma unroll
        for (int i = 0; i < 4; i++) {
            const int c   = tid + i * 256;
            const int isB = c >> 9;
            const int cc  = c & 511;
            const int row = cc >> 2, seg = cc & 3;
            const __half* src = (isB ? Bh : Ah) + (long long)row * K + k0 + seg * 8;
            const uint32_t dst = sbase + isB * TILE + row * RB + seg * 16;
            asm volatile("cp.async.cg.shared.global [%0], [%1], 16;"
                         :: "r"(dst), "l"(src) : "memory");
        }
    } else {
        #pragma unroll
        for (int i = 0; i < 8; i++) {
            const int c   = tid + i * 256;
            const int isB = c >> 10;
            const int cc  = c & 1023;
            const int row = cc >> 3, seg = cc & 7;
            if (TERMS == 2 && !isB && seg >= 4) continue;   // skip A-lo
            const __half* hp = isB ? Bh : Ah;
            const __half* lp = isB ? Bl : Al;
            const __half* src = (seg < 4)
                ? hp + (long long)row * K + k0 + seg * 8
                : lp + (long long)row * K + k0 + (seg - 4) * 8;
            const uint32_t dst = sbase + isB * TILE + row * RB +
                                 ((seg < 4) ? seg * 16 : 64 + (seg - 4) * 16);
            asm volatile("cp.async.cg.shared.global [%0], [%1], 16;"
                         :: "r"(dst), "l"(src) : "memory");
        }
    }
}

// R13 mainloop (grouped LDSM burst, term-ordered MMAs), templated on RB/ST.
template <int TERMS, int RB, int ST>
__device__ __forceinline__ void gemm_mainloop(
    uint32_t sb, const __half* Ah0, const __half* Al0,
    const __half* Bh0, const __half* Bl0,
    int K, int tid, int wm, int wn, uint32_t a_off, uint32_t b_off,
    float acc[2][8][4])
{
    constexpr int TILE  = 128 * RB;
    constexpr int STAGE = 2 * TILE;
    const int nch = K >> 5;
    #pragma unroll
    for (int s = 0; s < ST - 1; s++) {
        cp_issue<TERMS, RB>(sb + s * STAGE, Ah0, Al0, Bh0, Bl0, s * 32, K, tid);
        CP_COMMIT();
    }
    #pragma unroll 1
    for (int c = 0; c < nch; c++) {
        CP_WAIT(ST - 2);
        __syncthreads();
        const int nx = c + ST - 1;
        if (nx < nch)
            cp_issue<TERMS, RB>(sb + (nx % ST) * STAGE, Ah0, Al0, Bh0, Bl0,
                                nx * 32, K, tid);
        CP_COMMIT();

        const uint32_t asb = sb + (c % ST) * STAGE;
        const uint32_t bsb = asb + TILE;

        #pragma unroll
        for (int ks = 0; ks < 2; ks++) {
            const uint32_t kb = ks * 32;
            uint32_t ah[2][4], alo[2][4], bh[4][4], blo[4][4];
            #pragma unroll
            for (int mt = 0; mt < 2; mt++) {
                const uint32_t base = asb + (wm * 32 + mt * 16) * RB + kb + a_off;
                LDM4(ah[mt], base);
                if (TERMS == 3) LDM4(alo[mt], base + 64);
            }
            #pragma unroll
            for (int p = 0; p < 4; p++) {
                const uint32_t base = bsb + (wn * 64 + p * 16) * RB + kb + b_off;
                LDM4(bh[p], base);
                if (TERMS >= 2) LDM4(blo[p], base + 64);
            }
            #pragma unroll
            for (int nt = 0; nt < 8; nt++) {
                const uint32_t* bph = &bh[nt >> 1][(nt & 1) * 2];
                mma_f16(acc[0][nt], ah[0], bph);
                mma_f16(acc[1][nt], ah[1], bph);
            }
            if (TERMS >= 2) {
                #pragma unroll
                for (int nt = 0; nt < 8; nt++) {
                    const uint32_t* bpl = &blo[nt >> 1][(nt & 1) * 2];
                    mma_f16(acc[0][nt], ah[0], bpl);
                    mma_f16(acc[1][nt], ah[1], bpl);
                }
            }
            if (TERMS == 3) {
                #pragma unroll
                for (int nt = 0; nt < 8; nt++) {
                    const uint32_t* bph = &bh[nt >> 1][(nt & 1) * 2];
                    mma_f16(acc[0][nt], alo[0], bph);
                    mma_f16(acc[1][nt], alo[1], bph);
                }
            }
        }
    }
}

// ---------------------------------------------------------------------------
// gemm16<MODE, TERMS>: C = scale*(A @ B^T) + bias.
//   MODE 0: fp32 out (+bias).
//   MODE 2: fp16 hi out; if rsum != nullptr, divide by rowsum (PV normalize).
//   MODE 3: exp epilogue: u = exp(scale*acc - 12), fp16 Ph + partial row sums.
// ---------------------------------------------------------------------------
template <int MODE, int TERMS>
__global__ void __launch_bounds__(256, 2)
gemm16(const __half* __restrict__ Ah, const __half* __restrict__ Al,
       const __half* __restrict__ Bh, const __half* __restrict__ Bl,
       float* __restrict__ Cf, __half* __restrict__ Ch,
       const float* __restrict__ bias, float scale, int K, int ldC,
       long long sA, long long sB, long long sC,
       float* __restrict__ part, const float* __restrict__ rsum)
{
    constexpr int RB = (TERMS == 1) ? 80 : 144;
    constexpr int ST = (TERMS == 1) ? 4 : 3;
    extern __shared__ char smem[];
    const uint32_t sb = smem_u32(smem);
    const int tid = threadIdx.x, wid = tid >> 5, lane = tid & 31;
    const int g = lane >> 2, tg = lane & 3;
    const int wm = wid & 3, wn = wid >> 2;
    const long long m0 = (long long)blockIdx.y * 128;
    const long long n0 = (long long)blockIdx.x * 128;
    const long long zA = (long long)blockIdx.z * sA;
    const long long zB = (long long)blockIdx.z * sB;
    const long long zC = (long long)blockIdx.z * sC;

    const __half* Ah0 = Ah + zA + m0 * K;
    const __half* Al0 = (TERMS == 3) ? Al + zA + m0 * K : Ah0;
    const __half* Bh0 = Bh + zB + n0 * K;
    const __half* Bl0 = (TERMS >= 2) ? Bl + zB + n0 * K : Bh0;

    const int fj = lane >> 3, fr = lane & 7;
    const uint32_t a_off = ((fj & 1) * 8 + fr) * RB + (fj >> 1) * 16;
    const uint32_t b_off = ((fj >> 1) * 8 + fr) * RB + (fj & 1) * 16;

    float acc[2][8][4];
    #pragma unroll
    for (int i = 0; i < 2; i++)
        #pragma unroll
        for (int j = 0; j < 8; j++)
            #pragma unroll
            for (int l = 0; l < 4; l++) acc[i][j][l] = 0.0f;

    gemm_mainloop<TERMS, RB, ST>(sb, Ah0, Al0, Bh0, Bl0, K, tid, wm, wn,
                                 a_off, b_off, acc);

    if (MODE == 3) {
        float rs[2][2] = {{0.0f, 0.0f}, {0.0f, 0.0f}};
        #pragma unroll
        for (int nt = 0; nt < 8; nt++) {
            const long long ccol = n0 + wn * 64 + nt * 8 + tg * 2;
            #pragma unroll
            for (int mt = 0; mt < 2; mt++) {
                const long long rA = m0 + wm * 32 + mt * 16 + g;
                const long long rB = rA + 8;
                const float e0 = __expf(fmaf(acc[mt][nt][0], scale, -EXP_SHIFT));
                const float e1 = __expf(fmaf(acc[mt][nt][1], scale, -EXP_SHIFT));
                const float e2 = __expf(fmaf(acc[mt][nt][2], scale, -EXP_SHIFT));
                const float e3 = __expf(fmaf(acc[mt][nt][3], scale, -EXP_SHIFT));
                __half2 h0 = __floats2half2_rn(e0, e1);
                __half2 h1 = __floats2half2_rn(e2, e3);
                *(uint32_t*)(Ch + zC + rA * ldC + ccol) = *(uint32_t*)&h0;
                *(uint32_t*)(Ch + zC + rB * ldC + ccol) = *(uint32_t*)&h1;
                rs[mt][0] += e0 + e1;
                rs[mt][1] += e2 + e3;
            }
        }
        #pragma unroll
        for (int mt = 0; mt < 2; mt++)
            #pragma unroll
            for (int i = 0; i < 2; i++) {
                rs[mt][i] += __shfl_xor_sync(0xffffffffu, rs[mt][i], 1);
                rs[mt][i] += __shfl_xor_sync(0xffffffffu, rs[mt][i], 2);
            }
        if (tg == 0) {
            const long long rowbase = (long long)blockIdx.z * SEQ;
            const int pcol = blockIdx.x * 2 + wn;
            #pragma unroll
            for (int mt = 0; mt < 2; mt++) {
                const long long rA = m0 + wm * 32 + mt * 16 + g;
                part[(rowbase + rA) * 64 + pcol]     = rs[mt][0];
                part[(rowbase + rA + 8) * 64 + pcol] = rs[mt][1];
            }
        }
        return;
    }

    const float* rsz = (MODE == 2 && rsum) ? rsum + (long long)blockIdx.z * SEQ : nullptr;
    #pragma unroll
    for (int nt = 0; nt < 8; nt++) {
        const long long ccol = n0 + wn * 64 + nt * 8 + tg * 2;
        const float b0 = (MODE == 0 && bias) ? bias[ccol]     : 0.0f;
        const float b1 = (MODE == 0 && bias) ? bias[ccol + 1] : 0.0f;
        #pragma unroll
        for (int mt = 0; mt < 2; mt++) {
            const long long rA = m0 + wm * 32 + mt * 16 + g;
            const long long rB = rA + 8;
            float sA2 = scale, sB2 = scale;
            if (MODE == 2 && rsz) { sA2 = 1.0f / rsz[rA]; sB2 = 1.0f / rsz[rB]; }
            const float f0 = acc[mt][nt][0] * sA2 + b0;
            const float f1 = acc[mt][nt][1] * sA2 + b1;
            const float f2 = acc[mt][nt][2] * sB2 + b0;
            const float f3 = acc[mt][nt][3] * sB2 + b1;
            if (MODE == 0) {
                *(float2*)(Cf + zC + rA * ldC + ccol) = make_float2(f0, f1);
                *(float2*)(Cf + zC + rB * ldC + ccol) = make_float2(f2, f3);
            } else {
                __half2 h0 = __floats2half2_rn(f0, f1);
                __half2 h1 = __floats2half2_rn(f2, f3);
                *(uint32_t*)(Ch + zC + rA * ldC + ccol) = *(uint32_t*)&h0;
                *(uint32_t*)(Ch + zC + rB * ldC + ccol) = *(uint32_t*)&h1;
            }
        }
    }
}

// ---------------------------------------------------------------------------
// reduce_rows: rowsum[r] = sum of 64 partials.  One warp per row.
// ---------------------------------------------------------------------------
__global__ void __launch_bounds__(256)
reduce_rows(const float* __restrict__ part, float* __restrict__ rsum)
{
    const int r = (blockIdx.x * 256 + threadIdx.x) >> 5;
    const int lane = threadIdx.x & 31;
    if (r >= MFLAT) return;
    const float* p = part + (size_t)r * 64;
    float s = p[lane] + p[lane + 32];
    #pragma unroll
    for (int o = 16; o > 0; o >>= 1) s += __shfl_xor_sync(0xffffffffu, s, o);
    if (lane == 0) rsum[r] = s;
}

// ---------------------------------------------------------------------------
// proj3: fused q/k/v projection. z=0: qp split; z=1: kp split; z=2: vTh.
// ---------------------------------------------------------------------------
__global__ void __launch_bounds__(256, 2)
proj3(const __half* __restrict__ qh, const __half* __restrict__ ql,
      const __half* __restrict__ kh, const __half* __restrict__ kl,
      const __half* __restrict__ vh, const __half* __restrict__ vl,
      const __half* __restrict__ wqh, const __half* __restrict__ wql,
      const __half* __restrict__ wkh, const __half* __restrict__ wkl,
      const __half* __restrict__ wvh, const __half* __restrict__ wvl,
      __half* __restrict__ qph, __half* __restrict__ qpl,
      __half* __restrict__ kph, __half* __restrict__ kpl,
      __half* __restrict__ vTh,
      const float* __restrict__ b_q, const float* __restrict__ b_k,
      const float* __restrict__ b_v)
{
    constexpr int RB = 144;
    extern __shared__ char smem[];
    const uint32_t sb = smem_u32(smem);
    const int tid = threadIdx.x, wid = tid >> 5, lane = tid & 31;
    const int g = lane >> 2, tg = lane & 3;
    const int wm = wid & 3, wn = wid >> 2;
    const int z = blockIdx.z;
    const long long m0 = (long long)blockIdx.y * 128;
    const long long n0 = (long long)blockIdx.x * 128;
    const int K = DMODEL;

    const __half* Ah0 = ((z == 0) ? qh : (z == 1) ? kh : vh) + m0 * K;
    const __half* Al0 = ((z == 0) ? ql : (z == 1) ? kl : vl) + m0 * K;
    const __half* Bh0 = ((z == 0) ? wqh : (z == 1) ? wkh : wvh) + n0 * K;
    const __half* Bl0 = ((z == 0) ? wql : (z == 1) ? wkl : wvl) + n0 * K;
    const float* bias = (z == 0) ? b_q : (z == 1) ? b_k : b_v;

    const int fj = lane >> 3, fr = lane & 7;
    const uint32_t a_off = ((fj & 1) * 8 + fr) * RB + (fj >> 1) * 16;
    const uint32_t b_off = ((fj >> 1) * 8 + fr) * RB + (fj & 1) * 16;

    float acc[2][8][4];
    #pragma unroll
    for (int i = 0; i < 2; i++)
        #pragma unroll
        for (int j = 0; j < 8; j++)
            #pragma unroll
            for (int l = 0; l < 4; l++) acc[i][j][l] = 0.0f;

    gemm_mainloop<3, RB, 3>(sb, Ah0, Al0, Bh0, Bl0, K, tid, wm, wn,
                            a_off, b_off, acc);

    __half* Ch = (z == 0) ? qph : kph;
    __half* Cl = (z == 0) ? qpl : kpl;

    #pragma unroll
    for (int nt = 0; nt < 8; nt++) {
        const long long ccol = n0 + wn * 64 + nt * 8 + tg * 2;
        const float b0 = bias[ccol];
        const float b1 = bias[ccol + 1];
        #pragma unroll
        for (int mt = 0; mt < 2; mt++) {
            const long long rA = m0 + wm * 32 + mt * 16 + g;
            const long long rB = rA + 8;
            const float f0 = acc[mt][nt][0] + b0;
            const float f1 = acc[mt][nt][1] + b1;
            const float f2 = acc[mt][nt][2] + b0;
            const float f3 = acc[mt][nt][3] + b1;
            if (z < 2) {
                uint32_t h, l;
                split2(f0, f1, h, l);
                *(uint32_t*)(Ch + rA * PROJD + ccol) = h;
                *(uint32_t*)(Cl + rA * PROJD + ccol) = l;
                split2(f2, f3, h, l);
                *(uint32_t*)(Ch + rB * PROJD + ccol) = h;
                *(uint32_t*)(Cl + rB * PROJD + ccol) = l;
            } else {
                const long long zbA = rA >> 12, rbA = rA & 4095;
                const long long zbB = rB >> 12, rbB = rB & 4095;
                const long long baseA = zbA * ((long long)SEQ * PROJD);
                const long long baseB = zbB * ((long long)SEQ * PROJD);
                vTh[baseA + ccol * SEQ + rbA]       = __float2half_rn(f0);
                vTh[baseA + (ccol + 1) * SEQ + rbA] = __float2half_rn(f1);
                vTh[baseB + ccol * SEQ + rbB]       = __float2half_rn(f2);
                vTh[baseB + (ccol + 1) * SEQ + rbB] = __float2half_rn(f3);
            }
        }
    }
}

// ---------------------------------------------------------------------------
// Fused split of q, k, v (z selects tensor)
// ---------------------------------------------------------------------------
__global__ void __launch_bounds__(256)
split_qkv(const float* __restrict__ q, const float* __restrict__ k,
          const float* __restrict__ v,
          __half* __restrict__ qh, __half* __restrict__ ql,
          __half* __restrict__ kh, __half* __restrict__ kl,
          __half* __restrict__ vh, __half* __restrict__ vl, int n4)
{
    const int i = blockIdx.x * 256 + threadIdx.x;
    if (i >= n4) return;
    const int z = blockIdx.y;
    const float* in = (z == 0) ? q : (z == 1) ? k : v;
    __half* oh = (z == 0) ? qh : (z == 1) ? kh : vh;
    __half* ol = (z == 0) ? ql : (z == 1) ? kl : vl;
    float4 f = ((const float4*)in)[i];
    uint32_t h0, l0, h1, l1;
    split2(f.x, f.y, h0, l0);
    split2(f.z, f.w, h1, l1);
    ((uint32_t*)oh)[2 * i]     = h0;
    ((uint32_t*)oh)[2 * i + 1] = h1;
    ((uint32_t*)ol)[2 * i]     = l0;
    ((uint32_t*)ol)[2 * i + 1] = l1;
}

// ---------------------------------------------------------------------------
// Fused transpose+split of the four 512x512 weights (z selects weight)
// ---------------------------------------------------------------------------
__global__ void __launch_bounds__(256)
transpose_w4(const float* __restrict__ w0, const float* __restrict__ w1,
             const float* __restrict__ w2, const float* __restrict__ w3,
             __half* __restrict__ h0p, __half* __restrict__ l0p,
             __half* __restrict__ h1p, __half* __restrict__ l1p,
             __half* __restrict__ h2p, __half* __restrict__ l2p,
             __half* __restrict__ h3p, __half* __restrict__ l3p)
{
    __shared__ float t[32][33];
    const int z = blockIdx.z;
    const float* in = (z == 0) ? w0 : (z == 1) ? w1 : (z == 2) ? w2 : w3;
    __half* oh = (z == 0) ? h0p : (z == 1) ? h1p : (z == 2) ? h2p : h3p;
    __half* ol = (z == 0) ? l0p : (z == 1) ? l1p : (z == 2) ? l2p : l3p;
    const int tx = threadIdx.x, ty = threadIdx.y;
    const int c0 = blockIdx.x * 32, r0 = blockIdx.y * 32;
    #pragma unroll
    for (int i = ty; i < 32; i += 8)
        t[i][tx] = in[(r0 + i) * 512 + c0 + tx];
    __syncthreads();
    #pragma unroll
    for (int i = ty; i < 32; i += 8) {
        const int idx = (c0 + i) * 512 + r0 + tx;
        const float x = t[tx][i];
        const __half h = __float2half_rn(x);
        oh[idx] = h;
        ol[idx] = __float2half_rn(x - __half2float(h));
    }
}

// ---------------------------------------------------------------------------
// Launch
// ---------------------------------------------------------------------------
extern "C" void kernel_launch(void* const* d_in, const int* in_sizes, int n_in,
                              void* d_out, int out_size)
{
    const float* q     = (const float*)d_in[0];
    const float* k     = (const float*)d_in[1];
    const float* v     = (const float*)d_in[2];
    const float* w_q   = (const float*)d_in[3];
    const float* w_k   = (const float*)d_in[4];
    const float* w_v   = (const float*)d_in[5];
    const float* w_mha = (const float*)d_in[6];
    const float* b_q   = (const float*)d_in[7];
    const float* b_k   = (const float*)d_in[8];
    const float* b_v   = (const float*)d_in[9];
    const float* b_mha = (const float*)d_in[10];
    float* out = (float*)d_out;

    __half *qh,*ql,*kh,*kl,*vh,*vl, *wqh,*wql,*wkh,*wkl,*wvh,*wvl,*wmh,*wml;
    __half *qph,*qpl,*kph,*kpl,*vTh,*Ph,*dh;
    float *part, *rowsum;
    cudaGetSymbolAddress((void**)&qh,  g_qh);  cudaGetSymbolAddress((void**)&ql,  g_ql);
    cudaGetSymbolAddress((void**)&kh,  g_kh);  cudaGetSymbolAddress((void**)&kl,  g_kl);
    cudaGetSymbolAddress((void**)&vh,  g_vh);  cudaGetSymbolAddress((void**)&vl,  g_vl);
    cudaGetSymbolAddress((void**)&wqh, g_wqh); cudaGetSymbolAddress((void**)&wql, g_wql);
    cudaGetSymbolAddress((void**)&wkh, g_wkh); cudaGetSymbolAddress((void**)&wkl, g_wkl);
    cudaGetSymbolAddress((void**)&wvh, g_wvh); cudaGetSymbolAddress((void**)&wvl, g_wvl);
    cudaGetSymbolAddress((void**)&wmh, g_wmh); cudaGetSymbolAddress((void**)&wml, g_wml);
    cudaGetSymbolAddress((void**)&qph, g_qph); cudaGetSymbolAddress((void**)&qpl, g_qpl);
    cudaGetSymbolAddress((void**)&kph, g_kph); cudaGetSymbolAddress((void**)&kpl, g_kpl);
    cudaGetSymbolAddress((void**)&vTh, g_vTh);
    cudaGetSymbolAddress((void**)&Ph,  g_Ph);
    cudaGetSymbolAddress((void**)&dh,  g_dh);
    cudaGetSymbolAddress((void**)&part,   g_part);
    cudaGetSymbolAddress((void**)&rowsum, g_rowsum);

    const long long sP = (long long)SEQ * PROJD;
    const long long sS = (long long)SEQ * SEQ;

    cudaFuncSetAttribute(proj3,       cudaFuncAttributeMaxDynamicSharedMemorySize, SMEM_T3);
    cudaFuncSetAttribute(gemm16<3,3>, cudaFuncAttributeMaxDynamicSharedMemorySize, SMEM_T3);
    cudaFuncSetAttribute(gemm16<2,1>, cudaFuncAttributeMaxDynamicSharedMemorySize, SMEM_T1);
    cudaFuncSetAttribute(gemm16<0,1>, cudaFuncAttributeMaxDynamicSharedMemorySize, SMEM_T1);

    dim3 tblk(32, 8);

    // #0: split q,k,v
    const int n4 = MFLAT * DMODEL / 4;
    split_qkv<<<dim3(n4 / 256, 3), 256>>>(q, k, v, qh, ql, kh, kl, vh, vl, n4);
    // #1: transpose+split all 4 weights
    transpose_w4<<<dim3(16, 16, 4), tblk>>>(w_q, w_k, w_v, w_mha,
                                            wqh, wql, wkh, wkl, wvh, wvl, wmh, wml);
    // #2: fused projections
    proj3<<<dim3(PROJD / 128, MFLAT / 128, 3), 256, SMEM_T3>>>(
        qh, ql, kh, kl, vh, vl, wqh, wql, wkh, wkl, wvh, wvl,
        qph, qpl, kph, kpl, vTh, b_q, b_k, b_v);
    // #3: S GEMM with fused exp epilogue -> Ph (fp16) + partial row sums
    gemm16<3,3><<<dim3(SEQ / 128, SEQ / 128, BATCH), 256, SMEM_T3>>>(
        qph, qpl, kph, kpl, nullptr, Ph, nullptr, SCALE_QK,
        PROJD, SEQ, sP, sP, sS, part, nullptr);
    // #4: reduce partial sums -> rowsum
    reduce_rows<<<(MFLAT * 32 + 255) / 256, 256>>>(part, rowsum);
    // #5: dpa = (Ph @ vT^T) / rowsum  (1-term, ROWB=80, 4-stage)
    gemm16<2,1><<<dim3(PROJD / 128, SEQ / 128, BATCH), 256, SMEM_T1>>>(
        Ph, nullptr, vTh, nullptr, nullptr, dh, nullptr, 1.0f,
        SEQ, PROJD, sS, sP, sP, nullptr, rowsum);
    // #6: out = dpa @ wm^T + b_mha  (1-term, ROWB=80, 4-stage)
    gemm16<0,1><<<dim3(DMODEL / 128, MFLAT / 128, 1), 256, SMEM_T1>>>(
        dh, nullptr, wmh, nullptr, out, nullptr, b_mha, 1.0f,
        PROJD, DMODEL, 0, 0, 0, nullptr, nullptr);
}

// round 16
// speedup vs baseline: 1.5313x; 1.5313x over previous
#include <cuda_runtime.h>
#include <cuda_fp16.h>
#include <cstdint>

// ---------------------------------------------------------------------------
// Problem constants
// ---------------------------------------------------------------------------
#define BATCH 4
#define SEQ   4096
#define DMODEL 512
#define PROJD  512
#define MFLAT (BATCH * SEQ)
#define SCALE_QK 0.125f
#define EXP_SHIFT 12.0f

// ---------------------------------------------------------------------------
// Scratch (device globals)
// ---------------------------------------------------------------------------
__device__ __align__(16) __half g_qh [MFLAT * DMODEL];
__device__ __align__(16) __half g_ql [MFLAT * DMODEL];
__device__ __align__(16) __half g_kh [MFLAT * DMODEL];
__device__ __align__(16) __half g_kl [MFLAT * DMODEL];
__device__ __align__(16) __half g_vh [MFLAT * DMODEL];
__device__ __align__(16) __half g_vl [MFLAT * DMODEL];
__device__ __align__(16) __half g_wqh[PROJD * DMODEL];
__device__ __align__(16) __half g_wql[PROJD * DMODEL];
__device__ __align__(16) __half g_wkh[PROJD * DMODEL];
__device__ __align__(16) __half g_wkl[PROJD * DMODEL];
__device__ __align__(16) __half g_wvh[PROJD * DMODEL];
__device__ __align__(16) __half g_wvl[PROJD * DMODEL];
__device__ __align__(16) __half g_wmh[DMODEL * PROJD];
__device__ __align__(16) __half g_wml[DMODEL * PROJD];
__device__ __align__(16) __half g_qph[MFLAT * PROJD];
__device__ __align__(16) __half g_qpl[MFLAT * PROJD];
__device__ __align__(16) __half g_kph[MFLAT * PROJD];
__device__ __align__(16) __half g_kpl[MFLAT * PROJD];
__device__ __align__(16) __half g_vTh[MFLAT * PROJD];              // per-batch [512][4096]
__device__ __align__(16) __half g_Ph[(size_t)BATCH * SEQ * SEQ];   // exp(s-12), fp16
__device__ __align__(16) __half g_dh [MFLAT * PROJD];
__device__ float g_part[(size_t)MFLAT * 64];                       // per-row partial sums
__device__ float g_rowsum[MFLAT];

// ---------------------------------------------------------------------------
// Helpers
// ---------------------------------------------------------------------------
__device__ __forceinline__ uint32_t smem_u32(const void* p) {
    uint32_t a;
    asm("{ .reg .u64 t; cvta.to.shared.u64 t, %1; cvt.u32.u64 %0, t; }"
        : "=r"(a) : "l"(p));
    return a;
}

__device__ __forceinline__ void split2(float x, float y, uint32_t& hi, uint32_t& lo) {
    __half2 h = __floats2half2_rn(x, y);
    float2  f = __half22float2(h);
    __half2 l = __floats2half2_rn(x - f.x, y - f.y);
    hi = *(uint32_t*)&h;
    lo = *(uint32_t*)&l;
}

__device__ __forceinline__ void mma_f16(float* d, const uint32_t* a, const uint32_t* b) {
    asm volatile(
        "mma.sync.aligned.m16n8k16.row.col.f32.f16.f16.f32 "
        "{%0,%1,%2,%3}, {%4,%5,%6,%7}, {%8,%9}, {%0,%1,%2,%3};\n"
        : "+f"(d[0]), "+f"(d[1]), "+f"(d[2]), "+f"(d[3])
        : "r"(a[0]), "r"(a[1]), "r"(a[2]), "r"(a[3]),
          "r"(b[0]), "r"(b[1]));
}

#define LDM4(r, addr) \
    asm volatile("ldmatrix.sync.aligned.m8n8.x4.shared.b16 {%0,%1,%2,%3}, [%4];" \
        : "=r"((r)[0]), "=r"((r)[1]), "=r"((r)[2]), "=r"((r)[3]) : "r"(addr))

#define CP_COMMIT() asm volatile("cp.async.commit_group;" ::: "memory")
#define CP_WAIT(n)  asm volatile("cp.async.wait_group %0;" :: "n"(n) : "memory")

// ---------------------------------------------------------------------------
// Shared tile geometry: CTA 128x128, BK=32, 8 warps (4M x 2N),
// 3-stage cp.async ring, 2 CTA/SM.
// ---------------------------------------------------------------------------
#define STAGES 3
#define ROWB 144
#define TILE_BYTES (128 * ROWB)
#define STAGE_BYTES (2 * TILE_BYTES)
#define SMEM_TOTAL (STAGES * STAGE_BYTES)    // 110592

template <int TERMS>
__device__ __forceinline__ void cp_issue(uint32_t sbase,
    const __half* __restrict__ Ah, const __half* __restrict__ Al,
    const __half* __restrict__ Bh, const __half* __restrict__ Bl,
    int k0, int K, int tid)
{
    #pragma unroll
    for (int i = 0; i < 8; i++) {
        const int c   = tid + i * 256;
        const int isB = c >> 10;
        const int cc  = c & 1023;
        const int row = cc >> 3, seg = cc & 7;
        if (TERMS <= 2 && !isB && seg >= 4) continue;   // skip A-lo
        if (TERMS == 1 &&  isB && seg >= 4) continue;   // skip B-lo
        const __half* hp = isB ? Bh : Ah;
        const __half* lp = isB ? Bl : Al;
        const __half* src = (seg < 4)
            ? hp + (long long)row * K + k0 + seg * 8
            : lp + (long long)row * K + k0 + (seg - 4) * 8;
        const uint32_t dst = sbase + isB * TILE_BYTES + row * ROWB +
                             ((seg < 4) ? seg * 16 : 64 + (seg - 4) * 16);
        asm volatile("cp.async.cg.shared.global [%0], [%1], 16;"
                     :: "r"(dst), "l"(src) : "memory");
    }
}

template <int TERMS>
__device__ __forceinline__ void gemm_mainloop(
    uint32_t sb, const __half* Ah0, const __half* Al0,
    const __half* Bh0, const __half* Bl0,
    int K, int tid, int wm, int wn, uint32_t a_off, uint32_t b_off,
    float acc[2][8][4])
{
    const int nch = K >> 5;
    #pragma unroll
    for (int s = 0; s < STAGES - 1; s++) {
        cp_issue<TERMS>(sb + s * STAGE_BYTES, Ah0, Al0, Bh0, Bl0, s * 32, K, tid);
        CP_COMMIT();
    }
    #pragma unroll 1
    for (int c = 0; c < nch; c++) {
        CP_WAIT(STAGES - 2);
        __syncthreads();
        const int nx = c + STAGES - 1;
        if (nx < nch)
            cp_issue<TERMS>(sb + (nx % STAGES) * STAGE_BYTES, Ah0, Al0, Bh0, Bl0,
                            nx * 32, K, tid);
        CP_COMMIT();

        const uint32_t asb = sb + (c % STAGES) * STAGE_BYTES;
        const uint32_t bsb = asb + TILE_BYTES;

        #pragma unroll
        for (int ks = 0; ks < 2; ks++) {
            const uint32_t kb = ks * 32;
            uint32_t ah[2][4], alo[2][4], bh[4][4], blo[4][4];
            #pragma unroll
            for (int mt = 0; mt < 2; mt++) {
                const uint32_t base = asb + (wm * 32 + mt * 16) * ROWB + kb + a_off;
                LDM4(ah[mt], base);
                if (TERMS == 3) LDM4(alo[mt], base + 64);
            }
            #pragma unroll
            for (int p = 0; p < 4; p++) {
                const uint32_t base = bsb + (wn * 64 + p * 16) * ROWB + kb + b_off;
                LDM4(bh[p], base);
                if (TERMS >= 2) LDM4(blo[p], base + 64);
            }
            #pragma unroll
            for (int nt = 0; nt < 8; nt++) {
                const uint32_t* bph = &bh[nt >> 1][(nt & 1) * 2];
                mma_f16(acc[0][nt], ah[0], bph);
                mma_f16(acc[1][nt], ah[1], bph);
            }
            if (TERMS >= 2) {
                #pragma unroll
                for (int nt = 0; nt < 8; nt++) {
                    const uint32_t* bpl = &blo[nt >> 1][(nt & 1) * 2];
                    mma_f16(acc[0][nt], ah[0], bpl);
                    mma_f16(acc[1][nt], ah[1], bpl);
                }
            }
            if (TERMS == 3) {
                #pragma unroll
                for (int nt = 0; nt < 8; nt++) {
                    const uint32_t* bph = &bh[nt >> 1][(nt & 1) * 2];
                    mma_f16(acc[0][nt], alo[0], bph);
                    mma_f16(acc[1][nt], alo[1], bph);
                }
            }
        }
    }
}

// ---------------------------------------------------------------------------
// gemm16<MODE, TERMS>: C = scale*(A @ B^T) + bias.
//   MODE 0: fp32 out (+bias).
//   MODE 2: fp16 hi out; if rsum != nullptr, divide by rowsum (PV normalize).
//   MODE 3: exp epilogue: u = exp(scale*acc - 12), fp16 Ph + partial row sums.
// ---------------------------------------------------------------------------
template <int MODE, int TERMS>
__global__ void __launch_bounds__(256, 2)
gemm16(const __half* __restrict__ Ah, const __half* __restrict__ Al,
       const __half* __restrict__ Bh, const __half* __restrict__ Bl,
       float* __restrict__ Cf, __half* __restrict__ Ch,
       const float* __restrict__ bias, float scale, int K, int ldC,
       long long sA, long long sB, long long sC,
       float* __restrict__ part, const float* __restrict__ rsum)
{
    extern __shared__ char smem[];
    const uint32_t sb = smem_u32(smem);
    const int tid = threadIdx.x, wid = tid >> 5, lane = tid & 31;
    const int g = lane >> 2, tg = lane & 3;
    const int wm = wid & 3, wn = wid >> 2;
    const long long m0 = (long long)blockIdx.y * 128;
    const long long n0 = (long long)blockIdx.x * 128;
    const long long zA = (long long)blockIdx.z * sA;
    const long long zB = (long long)blockIdx.z * sB;
    const long long zC = (long long)blockIdx.z * sC;

    const __half* Ah0 = Ah + zA + m0 * K;
    const __half* Al0 = (TERMS == 3) ? Al + zA + m0 * K : Ah0;
    const __half* Bh0 = Bh + zB + n0 * K;
    const __half* Bl0 = (TERMS >= 2) ? Bl + zB + n0 * K : Bh0;

    const int fj = lane >> 3, fr = lane & 7;
    const uint32_t a_off = ((fj & 1) * 8 + fr) * ROWB + (fj >> 1) * 16;
    const uint32_t b_off = ((fj >> 1) * 8 + fr) * ROWB + (fj & 1) * 16;

    float acc[2][8][4];
    #pragma unroll
    for (int i = 0; i < 2; i++)
        #pragma unroll
        for (int j = 0; j < 8; j++)
            #pragma unroll
            for (int l = 0; l < 4; l++) acc[i][j][l] = 0.0f;

    gemm_mainloop<TERMS>(sb, Ah0, Al0, Bh0, Bl0, K, tid, wm, wn, a_off, b_off, acc);

    if (MODE == 3) {
        float rs[2][2] = {{0.0f, 0.0f}, {0.0f, 0.0f}};
        #pragma unroll
        for (int nt = 0; nt < 8; nt++) {
            const long long ccol = n0 + wn * 64 + nt * 8 + tg * 2;
            #pragma unroll
            for (int mt = 0; mt < 2; mt++) {
                const long long rA = m0 + wm * 32 + mt * 16 + g;
                const long long rB = rA + 8;
                const float e0 = __expf(fmaf(acc[mt][nt][0], scale, -EXP_SHIFT));
                const float e1 = __expf(fmaf(acc[mt][nt][1], scale, -EXP_SHIFT));
                const float e2 = __expf(fmaf(acc[mt][nt][2], scale, -EXP_SHIFT));
                const float e3 = __expf(fmaf(acc[mt][nt][3], scale, -EXP_SHIFT));
                __half2 h0 = __floats2half2_rn(e0, e1);
                __half2 h1 = __floats2half2_rn(e2, e3);
                *(uint32_t*)(Ch + zC + rA * ldC + ccol) = *(uint32_t*)&h0;
                *(uint32_t*)(Ch + zC + rB * ldC + ccol) = *(uint32_t*)&h1;
                rs[mt][0] += e0 + e1;
                rs[mt][1] += e2 + e3;
            }
        }
        #pragma unroll
        for (int mt = 0; mt < 2; mt++)
            #pragma unroll
            for (int i = 0; i < 2; i++) {
                rs[mt][i] += __shfl_xor_sync(0xffffffffu, rs[mt][i], 1);
                rs[mt][i] += __shfl_xor_sync(0xffffffffu, rs[mt][i], 2);
            }
        if (tg == 0) {
            const long long rowbase = (long long)blockIdx.z * SEQ;
            const int pcol = blockIdx.x * 2 + wn;
            #pragma unroll
            for (int mt = 0; mt < 2; mt++) {
                const long long rA = m0 + wm * 32 + mt * 16 + g;
                part[(rowbase + rA) * 64 + pcol]     = rs[mt][0];
                part[(rowbase + rA + 8) * 64 + pcol] = rs[mt][1];
            }
        }
        return;
    }

    const float* rsz = (MODE == 2 && rsum) ? rsum + (long long)blockIdx.z * SEQ : nullptr;
    #pragma unroll
    for (int nt = 0; nt < 8; nt++) {
        const long long ccol = n0 + wn * 64 + nt * 8 + tg * 2;
        const float b0 = (MODE == 0 && bias) ? bias[ccol]     : 0.0f;
        const float b1 = (MODE == 0 && bias) ? bias[ccol + 1] : 0.0f;
        #pragma unroll
        for (int mt = 0; mt < 2; mt++) {
            const long long rA = m0 + wm * 32 + mt * 16 + g;
            const long long rB = rA + 8;
            float sA2 = scale, sB2 = scale;
            if (MODE == 2 && rsz) { sA2 = 1.0f / rsz[rA]; sB2 = 1.0f / rsz[rB]; }
            const float f0 = acc[mt][nt][0] * sA2 + b0;
            const float f1 = acc[mt][nt][1] * sA2 + b1;
            const float f2 = acc[mt][nt][2] * sB2 + b0;
            const float f3 = acc[mt][nt][3] * sB2 + b1;
            if (MODE == 0) {
                *(float2*)(Cf + zC + rA * ldC + ccol) = make_float2(f0, f1);
                *(float2*)(Cf + zC + rB * ldC + ccol) = make_float2(f2, f3);
            } else {
                __half2 h0 = __floats2half2_rn(f0, f1);
                __half2 h1 = __floats2half2_rn(f2, f3);
                *(uint32_t*)(Ch + zC + rA * ldC + ccol) = *(uint32_t*)&h0;
                *(uint32_t*)(Ch + zC + rB * ldC + ccol) = *(uint32_t*)&h1;
            }
        }
    }
}

// ---------------------------------------------------------------------------
// reduce_rows: rowsum[r] = sum of 64 partials.  One warp per row.
// ---------------------------------------------------------------------------
__global__ void __launch_bounds__(256)
reduce_rows(const float* __restrict__ part, float* __restrict__ rsum)
{
    const int r = (blockIdx.x * 256 + threadIdx.x) >> 5;
    const int lane = threadIdx.x & 31;
    if (r >= MFLAT) return;
    const float* p = part + (size_t)r * 64;
    float s = p[lane] + p[lane + 32];
    #pragma unroll
    for (int o = 16; o > 0; o >>= 1) s += __shfl_xor_sync(0xffffffffu, s, o);
    if (lane == 0) rsum[r] = s;
}

// ---------------------------------------------------------------------------
// proj3: fused q/k/v projection. z=0: qp split; z=1: kp split; z=2: vTh.
// ---------------------------------------------------------------------------
__global__ void __launch_bounds__(256, 2)
proj3(const __half* __restrict__ qh, const __half* __restrict__ ql,
      const __half* __restrict__ kh, const __half* __restrict__ kl,
      const __half* __restrict__ vh, const __half* __restrict__ vl,
      const __half* __restrict__ wqh, const __half* __restrict__ wql,
      const __half* __restrict__ wkh, const __half* __restrict__ wkl,
      const __half* __restrict__ wvh, const __half* __restrict__ wvl,
      __half* __restrict__ qph, __half* __restrict__ qpl,
      __half* __restrict__ kph, __half* __restrict__ kpl,
      __half* __restrict__ vTh,
      const float* __restrict__ b_q, const float* __restrict__ b_k,
      const float* __restrict__ b_v)
{
    extern __shared__ char smem[];
    const uint32_t sb = smem_u32(smem);
    const int tid = threadIdx.x, wid = tid >> 5, lane = tid & 31;
    const int g = lane >> 2, tg = lane & 3;
    const int wm = wid & 3, wn = wid >> 2;
    const int z = blockIdx.z;
    const long long m0 = (long long)blockIdx.y * 128;
    const long long n0 = (long long)blockIdx.x * 128;
    const int K = DMODEL;

    const __half* Ah0 = ((z == 0) ? qh : (z == 1) ? kh : vh) + m0 * K;
    const __half* Al0 = ((z == 0) ? ql : (z == 1) ? kl : vl) + m0 * K;
    const __half* Bh0 = ((z == 0) ? wqh : (z == 1) ? wkh : wvh) + n0 * K;
    const __half* Bl0 = ((z == 0) ? wql : (z == 1) ? wkl : wvl) + n0 * K;
    const float* bias = (z == 0) ? b_q : (z == 1) ? b_k : b_v;

    const int fj = lane >> 3, fr = lane & 7;
    const uint32_t a_off = ((fj & 1) * 8 + fr) * ROWB + (fj >> 1) * 16;
    const uint32_t b_off = ((fj >> 1) * 8 + fr) * ROWB + (fj & 1) * 16;

    float acc[2][8][4];
    #pragma unroll
    for (int i = 0; i < 2; i++)
        #pragma unroll
        for (int j = 0; j < 8; j++)
            #pragma unroll
            for (int l = 0; l < 4; l++) acc[i][j][l] = 0.0f;

    gemm_mainloop<3>(sb, Ah0, Al0, Bh0, Bl0, K, tid, wm, wn, a_off, b_off, acc);

    __half* Ch = (z == 0) ? qph : kph;
    __half* Cl = (z == 0) ? qpl : kpl;

    #pragma unroll
    for (int nt = 0; nt < 8; nt++) {
        const long long ccol = n0 + wn * 64 + nt * 8 + tg * 2;
        const float b0 = bias[ccol];
        const float b1 = bias[ccol + 1];
        #pragma unroll
        for (int mt = 0; mt < 2; mt++) {
            const long long rA = m0 + wm * 32 + mt * 16 + g;
            const long long rB = rA + 8;
            const float f0 = acc[mt][nt][0] + b0;
            const float f1 = acc[mt][nt][1] + b1;
            const float f2 = acc[mt][nt][2] + b0;
            const float f3 = acc[mt][nt][3] + b1;
            if (z < 2) {
                uint32_t h, l;
                split2(f0, f1, h, l);
                *(uint32_t*)(Ch + rA * PROJD + ccol) = h;
                *(uint32_t*)(Cl + rA * PROJD + ccol) = l;
                split2(f2, f3, h, l);
                *(uint32_t*)(Ch + rB * PROJD + ccol) = h;
                *(uint32_t*)(Cl + rB * PROJD + ccol) = l;
            } else {
                const long long zbA = rA >> 12, rbA = rA & 4095;
                const long long zbB = rB >> 12, rbB = rB & 4095;
                const long long baseA = zbA * ((long long)SEQ * PROJD);
                const long long baseB = zbB * ((long long)SEQ * PROJD);
                vTh[baseA + ccol * SEQ + rbA]       = __float2half_rn(f0);
                vTh[baseA + (ccol + 1) * SEQ + rbA] = __float2half_rn(f1);
                vTh[baseB + ccol * SEQ + rbB]       = __float2half_rn(f2);
                vTh[baseB + (ccol + 1) * SEQ + rbB] = __float2half_rn(f3);
            }
        }
    }
}

// ---------------------------------------------------------------------------
// Fused split of q, k, v (z selects tensor)
// ---------------------------------------------------------------------------
__global__ void __launch_bounds__(256)
split_qkv(const float* __restrict__ q, const float* __restrict__ k,
          const float* __restrict__ v,
          __half* __restrict__ qh, __half* __restrict__ ql,
          __half* __restrict__ kh, __half* __restrict__ kl,
          __half* __restrict__ vh, __half* __restrict__ vl, int n4)
{
    const int i = blockIdx.x * 256 + threadIdx.x;
    if (i >= n4) return;
    const int z = blockIdx.y;
    const float* in = (z == 0) ? q : (z == 1) ? k : v;
    __half* oh = (z == 0) ? qh : (z == 1) ? kh : vh;
    __half* ol = (z == 0) ? ql : (z == 1) ? kl : vl;
    float4 f = ((const float4*)in)[i];
    uint32_t h0, l0, h1, l1;
    split2(f.x, f.y, h0, l0);
    split2(f.z, f.w, h1, l1);
    ((uint32_t*)oh)[2 * i]     = h0;
    ((uint32_t*)oh)[2 * i + 1] = h1;
    ((uint32_t*)ol)[2 * i]     = l0;
    ((uint32_t*)ol)[2 * i + 1] = l1;
}

// ---------------------------------------------------------------------------
// Fused transpose+split of the four 512x512 weights (z selects weight)
// ---------------------------------------------------------------------------
__global__ void __launch_bounds__(256)
transpose_w4(const float* __restrict__ w0, const float* __restrict__ w1,
             const float* __restrict__ w2, const float* __restrict__ w3,
             __half* __restrict__ h0p, __half* __restrict__ l0p,
             __half* __restrict__ h1p, __half* __restrict__ l1p,
             __half* __restrict__ h2p, __half* __restrict__ l2p,
             __half* __restrict__ h3p, __half* __restrict__ l3p)
{
    __shared__ float t[32][33];
    const int z = blockIdx.z;
    const float* in = (z == 0) ? w0 : (z == 1) ? w1 : (z == 2) ? w2 : w3;
    __half* oh = (z == 0) ? h0p : (z == 1) ? h1p : (z == 2) ? h2p : h3p;
    __half* ol = (z == 0) ? l0p : (z == 1) ? l1p : (z == 2) ? l2p : l3p;
    const int tx = threadIdx.x, ty = threadIdx.y;
    const int c0 = blockIdx.x * 32, r0 = blockIdx.y * 32;
    #pragma unroll
    for (int i = ty; i < 32; i += 8)
        t[i][tx] = in[(r0 + i) * 512 + c0 + tx];
    __syncthreads();
    #pragma unroll
    for (int i = ty; i < 32; i += 8) {
        const int idx = (c0 + i) * 512 + r0 + tx;
        const float x = t[tx][i];
        const __half h = __float2half_rn(x);
        oh[idx] = h;
        ol[idx] = __float2half_rn(x - __half2float(h));
    }
}

// ---------------------------------------------------------------------------
// Launch
// ---------------------------------------------------------------------------
extern "C" void kernel_launch(void* const* d_in, const int* in_sizes, int n_in,
                              void* d_out, int out_size)
{
    const float* q     = (const float*)d_in[0];
    const float* k     = (const float*)d_in[1];
    const float* v     = (const float*)d_in[2];
    const float* w_q   = (const float*)d_in[3];
    const float* w_k   = (const float*)d_in[4];
    const float* w_v   = (const float*)d_in[5];
    const float* w_mha = (const float*)d_in[6];
    const float* b_q   = (const float*)d_in[7];
    const float* b_k   = (const float*)d_in[8];
    const float* b_v   = (const float*)d_in[9];
    const float* b_mha = (const float*)d_in[10];
    float* out = (float*)d_out;

    __half *qh,*ql,*kh,*kl,*vh,*vl, *wqh,*wql,*wkh,*wkl,*wvh,*wvl,*wmh,*wml;
    __half *qph,*qpl,*kph,*kpl,*vTh,*Ph,*dh;
    float *part, *rowsum;
    cudaGetSymbolAddress((void**)&qh,  g_qh);  cudaGetSymbolAddress((void**)&ql,  g_ql);
    cudaGetSymbolAddress((void**)&kh,  g_kh);  cudaGetSymbolAddress((void**)&kl,  g_kl);
    cudaGetSymbolAddress((void**)&vh,  g_vh);  cudaGetSymbolAddress((void**)&vl,  g_vl);
    cudaGetSymbolAddress((void**)&wqh, g_wqh); cudaGetSymbolAddress((void**)&wql, g_wql);
    cudaGetSymbolAddress((void**)&wkh, g_wkh); cudaGetSymbolAddress((void**)&wkl, g_wkl);
    cudaGetSymbolAddress((void**)&wvh, g_wvh); cudaGetSymbolAddress((void**)&wvl, g_wvl);
    cudaGetSymbolAddress((void**)&wmh, g_wmh); cudaGetSymbolAddress((void**)&wml, g_wml);
    cudaGetSymbolAddress((void**)&qph, g_qph); cudaGetSymbolAddress((void**)&qpl, g_qpl);
    cudaGetSymbolAddress((void**)&kph, g_kph); cudaGetSymbolAddress((void**)&kpl, g_kpl);
    cudaGetSymbolAddress((void**)&vTh, g_vTh);
    cudaGetSymbolAddress((void**)&Ph,  g_Ph);
    cudaGetSymbolAddress((void**)&dh,  g_dh);
    cudaGetSymbolAddress((void**)&part,   g_part);
    cudaGetSymbolAddress((void**)&rowsum, g_rowsum);

    const long long sP = (long long)SEQ * PROJD;
    const long long sS = (long long)SEQ * SEQ;

    cudaFuncSetAttribute(proj3,       cudaFuncAttributeMaxDynamicSharedMemorySize, SMEM_TOTAL);
    cudaFuncSetAttribute(gemm16<3,3>, cudaFuncAttributeMaxDynamicSharedMemorySize, SMEM_TOTAL);
    cudaFuncSetAttribute(gemm16<2,1>, cudaFuncAttributeMaxDynamicSharedMemorySize, SMEM_TOTAL);
    cudaFuncSetAttribute(gemm16<0,1>, cudaFuncAttributeMaxDynamicSharedMemorySize, SMEM_TOTAL);

    dim3 tblk(32, 8);

    // #0: split q,k,v
    const int n4 = MFLAT * DMODEL / 4;
    split_qkv<<<dim3(n4 / 256, 3), 256>>>(q, k, v, qh, ql, kh, kl, vh, vl, n4);
    // #1: transpose+split all 4 weights
    transpose_w4<<<dim3(16, 16, 4), tblk>>>(w_q, w_k, w_v, w_mha,
                                            wqh, wql, wkh, wkl, wvh, wvl, wmh, wml);
    // #2: fused projections
    proj3<<<dim3(PROJD / 128, MFLAT / 128, 3), 256, SMEM_TOTAL>>>(
        qh, ql, kh, kl, vh, vl, wqh, wql, wkh, wkl, wvh, wvl,
        qph, qpl, kph, kpl, vTh, b_q, b_k, b_v);
    // #3: S GEMM with fused exp epilogue -> Ph (fp16) + partial row sums
    gemm16<3,3><<<dim3(SEQ / 128, SEQ / 128, BATCH), 256, SMEM_TOTAL>>>(
        qph, qpl, kph, kpl, nullptr, Ph, nullptr, SCALE_QK,
        PROJD, SEQ, sP, sP, sS, part, nullptr);
    // #4: reduce partial sums -> rowsum
    reduce_rows<<<(MFLAT * 32 + 255) / 256, 256>>>(part, rowsum);
    // #5: dpa = (Ph @ vT^T) / rowsum  (1-term, normalize in epilogue)
    gemm16<2,1><<<dim3(PROJD / 128, SEQ / 128, BATCH), 256, SMEM_TOTAL>>>(
        Ph, nullptr, vTh, nullptr, nullptr, dh, nullptr, 1.0f,
        SEQ, PROJD, sS, sP, sP, nullptr, rowsum);
    // #6: out = dpa @ wm^T + b_mha  (1-term)
    gemm16<0,1><<<dim3(DMODEL / 128, MFLAT / 128, 1), 256, SMEM_TOTAL>>>(
        dh, nullptr, wmh, nullptr, out, nullptr, b_mha, 1.0f,
        PROJD, DMODEL, 0, 0, 0, nullptr, nullptr);
}

// round 17
// speedup vs baseline: 1.5468x; 1.0101x over previous
#include <cuda_runtime.h>
#include <cuda_fp16.h>
#include <cstdint>

// ---------------------------------------------------------------------------
// Problem constants
// ---------------------------------------------------------------------------
#define BATCH 4
#define SEQ   4096
#define DMODEL 512
#define PROJD  512
#define MFLAT (BATCH * SEQ)
#define SCALE_QK 0.125f
#define EXP_SHIFT 12.0f

// ---------------------------------------------------------------------------
// Scratch (device globals)
// ---------------------------------------------------------------------------
__device__ __align__(16) __half g_qh [MFLAT * DMODEL];
__device__ __align__(16) __half g_ql [MFLAT * DMODEL];
__device__ __align__(16) __half g_kh [MFLAT * DMODEL];
__device__ __align__(16) __half g_kl [MFLAT * DMODEL];
__device__ __align__(16) __half g_vh [MFLAT * DMODEL];
__device__ __align__(16) __half g_vl [MFLAT * DMODEL];
__device__ __align__(16) __half g_wqh[PROJD * DMODEL];
__device__ __align__(16) __half g_wql[PROJD * DMODEL];
__device__ __align__(16) __half g_wkh[PROJD * DMODEL];
__device__ __align__(16) __half g_wkl[PROJD * DMODEL];
__device__ __align__(16) __half g_wvh[PROJD * DMODEL];
__device__ __align__(16) __half g_wvl[PROJD * DMODEL];
__device__ __align__(16) __half g_wmh[DMODEL * PROJD];
__device__ __align__(16) __half g_wml[DMODEL * PROJD];
__device__ __align__(16) __half g_qph[MFLAT * PROJD];
__device__ __align__(16) __half g_qpl[MFLAT * PROJD];
__device__ __align__(16) __half g_kph[MFLAT * PROJD];
__device__ __align__(16) __half g_kpl[MFLAT * PROJD];
__device__ __align__(16) __half g_vTh[MFLAT * PROJD];              // per-batch [512][4096]
__device__ __align__(16) __half g_Ph[(size_t)BATCH * SEQ * SEQ];   // exp(s-12), fp16
__device__ __align__(16) __half g_dh [MFLAT * PROJD];
__device__ float g_part[(size_t)MFLAT * 64];                       // per-row partial sums
__device__ float g_rowsum[MFLAT];

// ---------------------------------------------------------------------------
// Helpers
// ---------------------------------------------------------------------------
__device__ __forceinline__ uint32_t smem_u32(const void* p) {
    uint32_t a;
    asm("{ .reg .u64 t; cvta.to.shared.u64 t, %1; cvt.u32.u64 %0, t; }"
        : "=r"(a) : "l"(p));
    return a;
}

__device__ __forceinline__ void split2(float x, float y, uint32_t& hi, uint32_t& lo) {
    __half2 h = __floats2half2_rn(x, y);
    float2  f = __half22float2(h);
    __half2 l = __floats2half2_rn(x - f.x, y - f.y);
    hi = *(uint32_t*)&h;
    lo = *(uint32_t*)&l;
}

__device__ __forceinline__ void mma_f16(float* d, const uint32_t* a, const uint32_t* b) {
    asm volatile(
        "mma.sync.aligned.m16n8k16.row.col.f32.f16.f16.f32 "
        "{%0,%1,%2,%3}, {%4,%5,%6,%7}, {%8,%9}, {%0,%1,%2,%3};\n"
        : "+f"(d[0]), "+f"(d[1]), "+f"(d[2]), "+f"(d[3])
        : "r"(a[0]), "r"(a[1]), "r"(a[2]), "r"(a[3]),
          "r"(b[0]), "r"(b[1]));
}

#define LDM4(r, addr) \
    asm volatile("ldmatrix.sync.aligned.m8n8.x4.shared.b16 {%0,%1,%2,%3}, [%4];" \
        : "=r"((r)[0]), "=r"((r)[1]), "=r"((r)[2]), "=r"((r)[3]) : "r"(addr))

#define CP_COMMIT() asm volatile("cp.async.commit_group;" ::: "memory")
#define CP_WAIT(n)  asm volatile("cp.async.wait_group %0;" :: "n"(n) : "memory")

// ---------------------------------------------------------------------------
// Tile geometry, templated:
//   TERMS>=2: ROWB=144 (hi 64B | lo 64B | pad 16B), 3 stages  (110.6 KB)
//   TERMS==1: ROWB=80  (hi 64B | pad 16B),          4 stages  ( 81.9 KB)
// CTA 128x128, BK=32, 8 warps (4M x 2N), 2 CTA/SM in all cases.
// ---------------------------------------------------------------------------
#define SMEM_T3 (3 * 2 * 128 * 144)   // 110592
#define SMEM_T1 (4 * 2 * 128 * 80)    //  81920

template <int TERMS, int RB>
__device__ __forceinline__ void cp_issue(uint32_t sbase,
    const __half* __restrict__ Ah, const __half* __restrict__ Al,
    const __half* __restrict__ Bh, const __half* __restrict__ Bl,
    int k0, int K, int tid)
{
    constexpr int TILE = 128 * RB;
    if (TERMS == 1) {
        // 1024 x 16B chunks: A 512 (128 rows x 4 segs), B 512
        #pragma unroll
        for (int i = 0; i < 4; i++) {
            const int c   = tid + i * 256;
            const int isB = c >> 9;
            const int cc  = c & 511;
            const int row = cc >> 2, seg = cc & 3;
            const __half* src = (isB ? Bh : Ah) + (long long)row * K + k0 + seg * 8;
            const uint32_t dst = sbase + isB * TILE + row * RB + seg * 16;
            asm volatile("cp.async.cg.shared.global [%0], [%1], 16;"
                         :: "r"(dst), "l"(src) : "memory");
        }
    } else {
        #pragma unroll
        for (int i = 0; i < 8; i++) {
            const int c   = tid + i * 256;
            const int isB = c >> 10;
            const int cc  = c & 1023;
            const int row = cc >> 3, seg = cc & 7;
            if (TERMS == 2 && !isB && seg >= 4) continue;   // skip A-lo
            const __half* hp = isB ? Bh : Ah;
            const __half* lp = isB ? Bl : Al;
            const __half* src = (seg < 4)
                ? hp + (long long)row * K + k0 + seg * 8
                : lp + (long long)row * K + k0 + (seg - 4) * 8;
            const uint32_t dst = sbase + isB * TILE + row * RB +
                                 ((seg < 4) ? seg * 16 : 64 + (seg - 4) * 16);
            asm volatile("cp.async.cg.shared.global [%0], [%1], 16;"
                         :: "r"(dst), "l"(src) : "memory");
        }
    }
}

// R13 mainloop (grouped LDSM burst, term-ordered MMAs), templated on RB/ST.
template <int TERMS, int RB, int ST>
__device__ __forceinline__ void gemm_mainloop(
    uint32_t sb, const __half* Ah0, const __half* Al0,
    const __half* Bh0, const __half* Bl0,
    int K, int tid, int wm, int wn, uint32_t a_off, uint32_t b_off,
    float acc[2][8][4])
{
    constexpr int TILE  = 128 * RB;
    constexpr int STAGE = 2 * TILE;
    const int nch = K >> 5;
    #pragma unroll
    for (int s = 0; s < ST - 1; s++) {
        cp_issue<TERMS, RB>(sb + s * STAGE, Ah0, Al0, Bh0, Bl0, s * 32, K, tid);
        CP_COMMIT();
    }
    #pragma unroll 1
    for (int c = 0; c < nch; c++) {
        CP_WAIT(ST - 2);
        __syncthreads();
        const int nx = c + ST - 1;
        if (nx < nch)
            cp_issue<TERMS, RB>(sb + (nx % ST) * STAGE, Ah0, Al0, Bh0, Bl0,
                                nx * 32, K, tid);
        CP_COMMIT();

        const uint32_t asb = sb + (c % ST) * STAGE;
        const uint32_t bsb = asb + TILE;

        #pragma unroll
        for (int ks = 0; ks < 2; ks++) {
            const uint32_t kb = ks * 32;
            uint32_t ah[2][4], alo[2][4], bh[4][4], blo[4][4];
            #pragma unroll
            for (int mt = 0; mt < 2; mt++) {
                const uint32_t base = asb + (wm * 32 + mt * 16) * RB + kb + a_off;
                LDM4(ah[mt], base);
                if (TERMS == 3) LDM4(alo[mt], base + 64);
            }
            #pragma unroll
            for (int p = 0; p < 4; p++) {
                const uint32_t base = bsb + (wn * 64 + p * 16) * RB + kb + b_off;
                LDM4(bh[p], base);
                if (TERMS >= 2) LDM4(blo[p], base + 64);
            }
            #pragma unroll
            for (int nt = 0; nt < 8; nt++) {
                const uint32_t* bph = &bh[nt >> 1][(nt & 1) * 2];
                mma_f16(acc[0][nt], ah[0], bph);
                mma_f16(acc[1][nt], ah[1], bph);
            }
            if (TERMS >= 2) {
                #pragma unroll
                for (int nt = 0; nt < 8; nt++) {
                    const uint32_t* bpl = &blo[nt >> 1][(nt & 1) * 2];
                    mma_f16(acc[0][nt], ah[0], bpl);
                    mma_f16(acc[1][nt], ah[1], bpl);
                }
            }
            if (TERMS == 3) {
                #pragma unroll
                for (int nt = 0; nt < 8; nt++) {
                    const uint32_t* bph = &bh[nt >> 1][(nt & 1) * 2];
                    mma_f16(acc[0][nt], alo[0], bph);
                    mma_f16(acc[1][nt], alo[1], bph);
                }
            }
        }
    }
}

// ---------------------------------------------------------------------------
// gemm16<MODE, TERMS>: C = scale*(A @ B^T) + bias.
//   MODE 0: fp32 out (+bias).
//   MODE 2: fp16 hi out; if rsum != nullptr, divide by rowsum (PV normalize).
//   MODE 3: exp epilogue: u = exp(scale*acc - 12), fp16 Ph + partial row sums.
// ---------------------------------------------------------------------------
template <int MODE, int TERMS>
__global__ void __launch_bounds__(256, 2)
gemm16(const __half* __restrict__ Ah, const __half* __restrict__ Al,
       const __half* __restrict__ Bh, const __half* __restrict__ Bl,
       float* __restrict__ Cf, __half* __restrict__ Ch,
       const float* __restrict__ bias, float scale, int K, int ldC,
       long long sA, long long sB, long long sC,
       float* __restrict__ part, const float* __restrict__ rsum)
{
    constexpr int RB = (TERMS == 1) ? 80 : 144;
    constexpr int ST = (TERMS == 1) ? 4 : 3;
    extern __shared__ char smem[];
    const uint32_t sb = smem_u32(smem);
    const int tid = threadIdx.x, wid = tid >> 5, lane = tid & 31;
    const int g = lane >> 2, tg = lane & 3;
    const int wm = wid & 3, wn = wid >> 2;
    const long long m0 = (long long)blockIdx.y * 128;
    const long long n0 = (long long)blockIdx.x * 128;
    const long long zA = (long long)blockIdx.z * sA;
    const long long zB = (long long)blockIdx.z * sB;
    const long long zC = (long long)blockIdx.z * sC;

    const __half* Ah0 = Ah + zA + m0 * K;
    const __half* Al0 = (TERMS == 3) ? Al + zA + m0 * K : Ah0;
    const __half* Bh0 = Bh + zB + n0 * K;
    const __half* Bl0 = (TERMS >= 2) ? Bl + zB + n0 * K : Bh0;

    const int fj = lane >> 3, fr = lane & 7;
    const uint32_t a_off = ((fj & 1) * 8 + fr) * RB + (fj >> 1) * 16;
    const uint32_t b_off = ((fj >> 1) * 8 + fr) * RB + (fj & 1) * 16;

    float acc[2][8][4];
    #pragma unroll
    for (int i = 0; i < 2; i++)
        #pragma unroll
        for (int j = 0; j < 8; j++)
            #pragma unroll
            for (int l = 0; l < 4; l++) acc[i][j][l] = 0.0f;

    gemm_mainloop<TERMS, RB, ST>(sb, Ah0, Al0, Bh0, Bl0, K, tid, wm, wn,
                                 a_off, b_off, acc);

    if (MODE == 3) {
        float rs[2][2] = {{0.0f, 0.0f}, {0.0f, 0.0f}};
        #pragma unroll
        for (int nt = 0; nt < 8; nt++) {
            const long long ccol = n0 + wn * 64 + nt * 8 + tg * 2;
            #pragma unroll
            for (int mt = 0; mt < 2; mt++) {
                const long long rA = m0 + wm * 32 + mt * 16 + g;
                const long long rB = rA + 8;
                const float e0 = __expf(fmaf(acc[mt][nt][0], scale, -EXP_SHIFT));
                const float e1 = __expf(fmaf(acc[mt][nt][1], scale, -EXP_SHIFT));
                const float e2 = __expf(fmaf(acc[mt][nt][2], scale, -EXP_SHIFT));
                const float e3 = __expf(fmaf(acc[mt][nt][3], scale, -EXP_SHIFT));
                __half2 h0 = __floats2half2_rn(e0, e1);
                __half2 h1 = __floats2half2_rn(e2, e3);
                *(uint32_t*)(Ch + zC + rA * ldC + ccol) = *(uint32_t*)&h0;
                *(uint32_t*)(Ch + zC + rB * ldC + ccol) = *(uint32_t*)&h1;
                rs[mt][0] += e0 + e1;
                rs[mt][1] += e2 + e3;
            }
        }
        #pragma unroll
        for (int mt = 0; mt < 2; mt++)
            #pragma unroll
            for (int i = 0; i < 2; i++) {
                rs[mt][i] += __shfl_xor_sync(0xffffffffu, rs[mt][i], 1);
                rs[mt][i] += __shfl_xor_sync(0xffffffffu, rs[mt][i], 2);
            }
        if (tg == 0) {
            const long long rowbase = (long long)blockIdx.z * SEQ;
            const int pcol = blockIdx.x * 2 + wn;
            #pragma unroll
            for (int mt = 0; mt < 2; mt++) {
                const long long rA = m0 + wm * 32 + mt * 16 + g;
                part[(rowbase + rA) * 64 + pcol]     = rs[mt][0];
                part[(rowbase + rA + 8) * 64 + pcol] = rs[mt][1];
            }
        }
        return;
    }

    const float* rsz = (MODE == 2 && rsum) ? rsum + (long long)blockIdx.z * SEQ : nullptr;
    #pragma unroll
    for (int nt = 0; nt < 8; nt++) {
        const long long ccol = n0 + wn * 64 + nt * 8 + tg * 2;
        const float b0 = (MODE == 0 && bias) ? bias[ccol]     : 0.0f;
        const float b1 = (MODE == 0 && bias) ? bias[ccol + 1] : 0.0f;
        #pragma unroll
        for (int mt = 0; mt < 2; mt++) {
            const long long rA = m0 + wm * 32 + mt * 16 + g;
            const long long rB = rA + 8;
            float sA2 = scale, sB2 = scale;
            if (MODE == 2 && rsz) { sA2 = 1.0f / rsz[rA]; sB2 = 1.0f / rsz[rB]; }
            const float f0 = acc[mt][nt][0] * sA2 + b0;
            const float f1 = acc[mt][nt][1] * sA2 + b1;
            const float f2 = acc[mt][nt][2] * sB2 + b0;
            const float f3 = acc[mt][nt][3] * sB2 + b1;
            if (MODE == 0) {
                *(float2*)(Cf + zC + rA * ldC + ccol) = make_float2(f0, f1);
                *(float2*)(Cf + zC + rB * ldC + ccol) = make_float2(f2, f3);
            } else {
                __half2 h0 = __floats2half2_rn(f0, f1);
                __half2 h1 = __floats2half2_rn(f2, f3);
                *(uint32_t*)(Ch + zC + rA * ldC + ccol) = *(uint32_t*)&h0;
                *(uint32_t*)(Ch + zC + rB * ldC + ccol) = *(uint32_t*)&h1;
            }
        }
    }
}

// ---------------------------------------------------------------------------
// reduce_rows: rowsum[r] = sum of 64 partials.  One warp per row.
// ---------------------------------------------------------------------------
__global__ void __launch_bounds__(256)
reduce_rows(const float* __restrict__ part, float* __restrict__ rsum)
{
    const int r = (blockIdx.x * 256 + threadIdx.x) >> 5;
    const int lane = threadIdx.x & 31;
    if (r >= MFLAT) return;
    const float* p = part + (size_t)r * 64;
    float s = p[lane] + p[lane + 32];
    #pragma unroll
    for (int o = 16; o > 0; o >>= 1) s += __shfl_xor_sync(0xffffffffu, s, o);
    if (lane == 0) rsum[r] = s;
}

// ---------------------------------------------------------------------------
// proj3: fused q/k/v projection. z=0: qp split; z=1: kp split; z=2: vTh.
// ---------------------------------------------------------------------------
__global__ void __launch_bounds__(256, 2)
proj3(const __half* __restrict__ qh, const __half* __restrict__ ql,
      const __half* __restrict__ kh, const __half* __restrict__ kl,
      const __half* __restrict__ vh, const __half* __restrict__ vl,
      const __half* __restrict__ wqh, const __half* __restrict__ wql,
      const __half* __restrict__ wkh, const __half* __restrict__ wkl,
      const __half* __restrict__ wvh, const __half* __restrict__ wvl,
      __half* __restrict__ qph, __half* __restrict__ qpl,
      __half* __restrict__ kph, __half* __restrict__ kpl,
      __half* __restrict__ vTh,
      const float* __restrict__ b_q, const float* __restrict__ b_k,
      const float* __restrict__ b_v)
{
    constexpr int RB = 144;
    extern __shared__ char smem[];
    const uint32_t sb = smem_u32(smem);
    const int tid = threadIdx.x, wid = tid >> 5, lane = tid & 31;
    const int g = lane >> 2, tg = lane & 3;
    const int wm = wid & 3, wn = wid >> 2;
    const int z = blockIdx.z;
    const long long m0 = (long long)blockIdx.y * 128;
    const long long n0 = (long long)blockIdx.x * 128;
    const int K = DMODEL;

    const __half* Ah0 = ((z == 0) ? qh : (z == 1) ? kh : vh) + m0 * K;
    const __half* Al0 = ((z == 0) ? ql : (z == 1) ? kl : vl) + m0 * K;
    const __half* Bh0 = ((z == 0) ? wqh : (z == 1) ? wkh : wvh) + n0 * K;
    const __half* Bl0 = ((z == 0) ? wql : (z == 1) ? wkl : wvl) + n0 * K;
    const float* bias = (z == 0) ? b_q : (z == 1) ? b_k : b_v;

    const int fj = lane >> 3, fr = lane & 7;
    const uint32_t a_off = ((fj & 1) * 8 + fr) * RB + (fj >> 1) * 16;
    const uint32_t b_off = ((fj >> 1) * 8 + fr) * RB + (fj & 1) * 16;

    float acc[2][8][4];
    #pragma unroll
    for (int i = 0; i < 2; i++)
        #pragma unroll
        for (int j = 0; j < 8; j++)
            #pragma unroll
            for (int l = 0; l < 4; l++) acc[i][j][l] = 0.0f;

    gemm_mainloop<3, RB, 3>(sb, Ah0, Al0, Bh0, Bl0, K, tid, wm, wn,
                            a_off, b_off, acc);

    __half* Ch = (z == 0) ? qph : kph;
    __half* Cl = (z == 0) ? qpl : kpl;

    #pragma unroll
    for (int nt = 0; nt < 8; nt++) {
        const long long ccol = n0 + wn * 64 + nt * 8 + tg * 2;
        const float b0 = bias[ccol];
        const float b1 = bias[ccol + 1];
        #pragma unroll
        for (int mt = 0; mt < 2; mt++) {
            const long long rA = m0 + wm * 32 + mt * 16 + g;
            const long long rB = rA + 8;
            const float f0 = acc[mt][nt][0] + b0;
            const float f1 = acc[mt][nt][1] + b1;
            const float f2 = acc[mt][nt][2] + b0;
            const float f3 = acc[mt][nt][3] + b1;
            if (z < 2) {
                uint32_t h, l;
                split2(f0, f1, h, l);
                *(uint32_t*)(Ch + rA * PROJD + ccol) = h;
                *(uint32_t*)(Cl + rA * PROJD + ccol) = l;
                split2(f2, f3, h, l);
                *(uint32_t*)(Ch + rB * PROJD + ccol) = h;
                *(uint32_t*)(Cl + rB * PROJD + ccol) = l;
            } else {
                const long long zbA = rA >> 12, rbA = rA & 4095;
                const long long zbB = rB >> 12, rbB = rB & 4095;
                const long long baseA = zbA * ((long long)SEQ * PROJD);
                const long long baseB = zbB * ((long long)SEQ * PROJD);
                vTh[baseA + ccol * SEQ + rbA]       = __float2half_rn(f0);
                vTh[baseA + (ccol + 1) * SEQ + rbA] = __float2half_rn(f1);
                vTh[baseB + ccol * SEQ + rbB]       = __float2half_rn(f2);
                vTh[baseB + (ccol + 1) * SEQ + rbB] = __float2half_rn(f3);
            }
        }
    }
}

// ---------------------------------------------------------------------------
// Fused split of q, k, v (z selects tensor)
// ---------------------------------------------------------------------------
__global__ void __launch_bounds__(256)
split_qkv(const float* __restrict__ q, const float* __restrict__ k,
          const float* __restrict__ v,
          __half* __restrict__ qh, __half* __restrict__ ql,
          __half* __restrict__ kh, __half* __restrict__ kl,
          __half* __restrict__ vh, __half* __restrict__ vl, int n4)
{
    const int i = blockIdx.x * 256 + threadIdx.x;
    if (i >= n4) return;
    const int z = blockIdx.y;
    const float* in = (z == 0) ? q : (z == 1) ? k : v;
    __half* oh = (z == 0) ? qh : (z == 1) ? kh : vh;
    __half* ol = (z == 0) ? ql : (z == 1) ? kl : vl;
    float4 f = ((const float4*)in)[i];
    uint32_t h0, l0, h1, l1;
    split2(f.x, f.y, h0, l0);
    split2(f.z, f.w, h1, l1);
    ((uint32_t*)oh)[2 * i]     = h0;
    ((uint32_t*)oh)[2 * i + 1] = h1;
    ((uint32_t*)ol)[2 * i]     = l0;
    ((uint32_t*)ol)[2 * i + 1] = l1;
}

// ---------------------------------------------------------------------------
// Fused transpose+split of the four 512x512 weights (z selects weight)
// ---------------------------------------------------------------------------
__global__ void __launch_bounds__(256)
transpose_w4(const float* __restrict__ w0, const float* __restrict__ w1,
             const float* __restrict__ w2, const float* __restrict__ w3,
             __half* __restrict__ h0p, __half* __restrict__ l0p,
             __half* __restrict__ h1p, __half* __restrict__ l1p,
             __half* __restrict__ h2p, __half* __restrict__ l2p,
             __half* __restrict__ h3p, __half* __restrict__ l3p)
{
    __shared__ float t[32][33];
    const int z = blockIdx.z;
    const float* in = (z == 0) ? w0 : (z == 1) ? w1 : (z == 2) ? w2 : w3;
    __half* oh = (z == 0) ? h0p : (z == 1) ? h1p : (z == 2) ? h2p : h3p;
    __half* ol = (z == 0) ? l0p : (z == 1) ? l1p : (z == 2) ? l2p : l3p;
    const int tx = threadIdx.x, ty = threadIdx.y;
    const int c0 = blockIdx.x * 32, r0 = blockIdx.y * 32;
    #pragma unroll
    for (int i = ty; i < 32; i += 8)
        t[i][tx] = in[(r0 + i) * 512 + c0 + tx];
    __syncthreads();
    #pragma unroll
    for (int i = ty; i < 32; i += 8) {
        const int idx = (c0 + i) * 512 + r0 + tx;
        const float x = t[tx][i];
        const __half h = __float2half_rn(x);
        oh[idx] = h;
        ol[idx] = __float2half_rn(x - __half2float(h));
    }
}

// ---------------------------------------------------------------------------
// Launch
// ---------------------------------------------------------------------------
extern "C" void kernel_launch(void* const* d_in, const int* in_sizes, int n_in,
                              void* d_out, int out_size)
{
    const float* q     = (const float*)d_in[0];
    const float* k     = (const float*)d_in[1];
    const float* v     = (const float*)d_in[2];
    const float* w_q   = (const float*)d_in[3];
    const float* w_k   = (const float*)d_in[4];
    const float* w_v   = (const float*)d_in[5];
    const float* w_mha = (const float*)d_in[6];
    const float* b_q   = (const float*)d_in[7];
    const float* b_k   = (const float*)d_in[8];
    const float* b_v   = (const float*)d_in[9];
    const float* b_mha = (const float*)d_in[10];
    float* out = (float*)d_out;

    __half *qh,*ql,*kh,*kl,*vh,*vl, *wqh,*wql,*wkh,*wkl,*wvh,*wvl,*wmh,*wml;
    __half *qph,*qpl,*kph,*kpl,*vTh,*Ph,*dh;
    float *part, *rowsum;
    cudaGetSymbolAddress((void**)&qh,  g_qh);  cudaGetSymbolAddress((void**)&ql,  g_ql);
    cudaGetSymbolAddress((void**)&kh,  g_kh);  cudaGetSymbolAddress((void**)&kl,  g_kl);
    cudaGetSymbolAddress((void**)&vh,  g_vh);  cudaGetSymbolAddress((void**)&vl,  g_vl);
    cudaGetSymbolAddress((void**)&wqh, g_wqh); cudaGetSymbolAddress((void**)&wql, g_wql);
    cudaGetSymbolAddress((void**)&wkh, g_wkh); cudaGetSymbolAddress((void**)&wkl, g_wkl);
    cudaGetSymbolAddress((void**)&wvh, g_wvh); cudaGetSymbolAddress((void**)&wvl, g_wvl);
    cudaGetSymbolAddress((void**)&wmh, g_wmh); cudaGetSymbolAddress((void**)&wml, g_wml);
    cudaGetSymbolAddress((void**)&qph, g_qph); cudaGetSymbolAddress((void**)&qpl, g_qpl);
    cudaGetSymbolAddress((void**)&kph, g_kph); cudaGetSymbolAddress((void**)&kpl, g_kpl);
    cudaGetSymbolAddress((void**)&vTh, g_vTh);
    cudaGetSymbolAddress((void**)&Ph,  g_Ph);
    cudaGetSymbolAddress((void**)&dh,  g_dh);
    cudaGetSymbolAddress((void**)&part,   g_part);
    cudaGetSymbolAddress((void**)&rowsum, g_rowsum);

    const long long sP = (long long)SEQ * PROJD;
    const long long sS = (long long)SEQ * SEQ;

    cudaFuncSetAttribute(proj3,       cudaFuncAttributeMaxDynamicSharedMemorySize, SMEM_T3);
    cudaFuncSetAttribute(gemm16<3,3>, cudaFuncAttributeMaxDynamicSharedMemorySize, SMEM_T3);
    cudaFuncSetAttribute(gemm16<2,1>, cudaFuncAttributeMaxDynamicSharedMemorySize, SMEM_T1);
    cudaFuncSetAttribute(gemm16<0,1>, cudaFuncAttributeMaxDynamicSharedMemorySize, SMEM_T1);

    dim3 tblk(32, 8);

    // #0: split q,k,v
    const int n4 = MFLAT * DMODEL / 4;
    split_qkv<<<dim3(n4 / 256, 3), 256>>>(q, k, v, qh, ql, kh, kl, vh, vl, n4);
    // #1: transpose+split all 4 weights
    transpose_w4<<<dim3(16, 16, 4), tblk>>>(w_q, w_k, w_v, w_mha,
                                            wqh, wql, wkh, wkl, wvh, wvl, wmh, wml);
    // #2: fused projections
    proj3<<<dim3(PROJD / 128, MFLAT / 128, 3), 256, SMEM_T3>>>(
        qh, ql, kh, kl, vh, vl, wqh, wql, wkh, wkl, wvh, wvl,
        qph, qpl, kph, kpl, vTh, b_q, b_k, b_v);
    // #3: S GEMM with fused exp epilogue -> Ph (fp16) + partial row sums
    gemm16<3,3><<<dim3(SEQ / 128, SEQ / 128, BATCH), 256, SMEM_T3>>>(
        qph, qpl, kph, kpl, nullptr, Ph, nullptr, SCALE_QK,
        PROJD, SEQ, sP, sP, sS, part, nullptr);
    // #4: reduce partial sums -> rowsum
    reduce_rows<<<(MFLAT * 32 + 255) / 256, 256>>>(part, rowsum);
    // #5: dpa = (Ph @ vT^T) / rowsum  (1-term, ROWB=80, 4-stage)
    gemm16<2,1><<<dim3(PROJD / 128, SEQ / 128, BATCH), 256, SMEM_T1>>>(
        Ph, nullptr, vTh, nullptr, nullptr, dh, nullptr, 1.0f,
        SEQ, PROJD, sS, sP, sP, nullptr, rowsum);
    // #6: out = dpa @ wm^T + b_mha  (1-term, ROWB=80, 4-stage)
    gemm16<0,1><<<dim3(DMODEL / 128, MFLAT / 128, 1), 256, SMEM_T1>>>(
        dh, nullptr, wmh, nullptr, out, nullptr, b_mha, 1.0f,
        PROJD, DMODEL, 0, 0, 0, nullptr, nullptr);
}